// round 14
// baseline (speedup 1.0000x reference)
#include <cuda_runtime.h>
#include <cuda_bf16.h>
#include <cstdint>

// BasicLS: per-batch least squares.
// For each b: A = [-x[:,1:4], 1]  (32x4), r = x[:,0].
// out[b] = (A^T A)^{-1} A^T r   (4 floats), via normal equations + Cholesky.
//
// TMA-bulk streaming pipeline (decisive bandwidth experiment):
//   - tile = 32 batches = 16 KB; double-buffered static smem (2 x 16 KB).
//   - thread 0 issues cp.async.bulk.shared::cta.global (hardware-sequenced
//     full-line stream, bypasses the per-thread L1tex request path that
//     capped six LDG-based designs at 67-74% DRAM).
//   - depth-2 pipeline: issue tile i+1, then mbarrier-wait tile i, compute,
//     __syncthreads (makes buffer reuse at i+2 safe).
//   - compute = proven 4-lane scheme: 4 threads/batch, 13 partial sums,
//     2 shfl_xor steps, Cholesky solve on sub==0.

static constexpr int TILE_BATCH = 32;                  // batches per tile
static constexpr int TILE_F4    = TILE_BATCH * 32;     // 1024 float4 = 16 KB
static constexpr int TILE_BYTES = TILE_F4 * 16;

__device__ __forceinline__ void mbar_init(uint32_t addr, uint32_t count) {
    asm volatile("mbarrier.init.shared.b64 [%0], %1;" :: "r"(addr), "r"(count) : "memory");
}
__device__ __forceinline__ void mbar_expect_tx(uint32_t addr, uint32_t bytes) {
    asm volatile("mbarrier.arrive.expect_tx.shared.b64 _, [%0], %1;"
                 :: "r"(addr), "r"(bytes) : "memory");
}
__device__ __forceinline__ void mbar_wait(uint32_t addr, uint32_t parity) {
    asm volatile(
        "{\n\t.reg .pred P;\n"
        "WAIT_%=:\n\t"
        "mbarrier.try_wait.parity.acquire.cta.shared::cta.b64 P, [%0], %1, 0x989680;\n\t"
        "@P bra DONE_%=;\n\t"
        "bra WAIT_%=;\n"
        "DONE_%=:\n\t}"
        :: "r"(addr), "r"(parity) : "memory");
}
__device__ __forceinline__ void tma_bulk_load(uint32_t dst, const void* src,
                                              uint32_t bytes, uint32_t mbar) {
    asm volatile(
        "cp.async.bulk.shared::cta.global.mbarrier::complete_tx::bytes [%0], [%1], %2, [%3];"
        :: "r"(dst), "l"(src), "r"(bytes), "r"(mbar) : "memory");
}

__global__ __launch_bounds__(128, 7)
void basic_ls_kernel(const float4* __restrict__ x,
                     float4* __restrict__ out,
                     int nTiles)
{
    __shared__ __align__(128) float4 buf[2][TILE_F4];   // 32 KB
    __shared__ __align__(8) unsigned long long mbar[2];

    const int t = threadIdx.x;
    const uint32_t mb0 = (uint32_t)__cvta_generic_to_shared(&mbar[0]);
    const uint32_t mb1 = (uint32_t)__cvta_generic_to_shared(&mbar[1]);
    const uint32_t sb0 = (uint32_t)__cvta_generic_to_shared(&buf[0][0]);
    const uint32_t sb1 = (uint32_t)__cvta_generic_to_shared(&buf[1][0]);

    if (t == 0) { mbar_init(mb0, 1); mbar_init(mb1, 1); }
    __syncthreads();

    const int bid  = (int)blockIdx.x;
    const int grid = (int)gridDim.x;
    const int myTiles = (nTiles - bid + grid - 1) / grid;

    // Compute-side constants (4 threads per batch, 32 batches, 4 warps).
    const int lane  = t & 31;
    const int warp  = t >> 5;            // 0..3
    const int group = lane >> 2;         // 0..7
    const int sub   = lane & 3;          // 0..3
    const int batchInTile = warp * 8 + group;          // 0..31
    const float4* __restrict__ bbase0 = &buf[0][batchInTile * 32 + sub];
    const float4* __restrict__ bbase1 = &buf[1][batchInTile * 32 + sub];

    // Prologue: load tile 0.
    if (myTiles > 0 && t == 0) {
        mbar_expect_tx(mb0, TILE_BYTES);
        tma_bulk_load(sb0, x + (size_t)bid * TILE_F4, TILE_BYTES, mb0);
    }

    for (int i = 0; i < myTiles; ++i) {
        const int p  = i & 1;
        const int T  = bid + i * grid;

        // Issue the next tile into the other buffer (safe: that buffer's
        // readers all passed the __syncthreads at the end of iteration i-1).
        if (i + 1 < myTiles && t == 0) {
            const int Tn = T + grid;
            const uint32_t mbn = p ? mb0 : mb1;
            const uint32_t sbn = p ? sb0 : sb1;
            mbar_expect_tx(mbn, TILE_BYTES);
            tma_bulk_load(sbn, x + (size_t)Tn * TILE_F4, TILE_BYTES, mbn);
        }

        // Wait for tile i.
        mbar_wait(p ? mb1 : mb0, (uint32_t)((i >> 1) & 1));

        const float4* __restrict__ bb = p ? bbase1 : bbase0;

        // ---- Accumulate normal-equation sums over this thread's 8 rows. ----
        float sx1 = 0.f, sx2 = 0.f, sx3 = 0.f, sr = 0.f;
        float s11 = 0.f, s12 = 0.f, s13 = 0.f;
        float s22 = 0.f, s23 = 0.f, s33 = 0.f;
        float t1  = 0.f, t2  = 0.f, t3  = 0.f;

#pragma unroll
        for (int k = 0; k < 8; ++k) {
            const float4 v = bb[k * 4];          // LDS.128
            const float r = v.x, a = v.y, b = v.z, c = v.w;
            sx1 += a;  sx2 += b;  sx3 += c;  sr += r;
            s11 = fmaf(a, a, s11);
            s12 = fmaf(a, b, s12);
            s13 = fmaf(a, c, s13);
            s22 = fmaf(b, b, s22);
            s23 = fmaf(b, c, s23);
            s33 = fmaf(c, c, s33);
            t1  = fmaf(a, r, t1);
            t2  = fmaf(b, r, t2);
            t3  = fmaf(c, r, t3);
        }

        // ---- Reduce across the 4-lane group. ----
#pragma unroll
        for (int off = 1; off <= 2; off <<= 1) {
            sx1 += __shfl_xor_sync(0xffffffffu, sx1, off);
            sx2 += __shfl_xor_sync(0xffffffffu, sx2, off);
            sx3 += __shfl_xor_sync(0xffffffffu, sx3, off);
            sr  += __shfl_xor_sync(0xffffffffu, sr,  off);
            s11 += __shfl_xor_sync(0xffffffffu, s11, off);
            s12 += __shfl_xor_sync(0xffffffffu, s12, off);
            s13 += __shfl_xor_sync(0xffffffffu, s13, off);
            s22 += __shfl_xor_sync(0xffffffffu, s22, off);
            s23 += __shfl_xor_sync(0xffffffffu, s23, off);
            s33 += __shfl_xor_sync(0xffffffffu, s33, off);
            t1  += __shfl_xor_sync(0xffffffffu, t1,  off);
            t2  += __shfl_xor_sync(0xffffffffu, t2,  off);
            t3  += __shfl_xor_sync(0xffffffffu, t3,  off);
        }

        if (sub == 0) {
            const float g11 = s11, g12 = s12, g13 = s13, g14 = -sx1;
            const float g22 = s22, g23 = s23, g24 = -sx2;
            const float g33 = s33, g34 = -sx3;
            const float g44 = 32.0f;             // M rows, a4 == 1
            const float b1 = -t1, b2 = -t2, b3 = -t3, b4 = sr;

            const float l11 = sqrtf(g11);
            const float i11 = 1.0f / l11;
            const float l21 = g12 * i11;
            const float l31 = g13 * i11;
            const float l41 = g14 * i11;

            const float d22 = g22 - l21 * l21;
            const float l22 = sqrtf(d22);
            const float i22 = 1.0f / l22;
            const float l32 = (g23 - l31 * l21) * i22;
            const float l42 = (g24 - l41 * l21) * i22;

            const float d33 = g33 - l31 * l31 - l32 * l32;
            const float l33 = sqrtf(d33);
            const float i33 = 1.0f / l33;
            const float l43 = (g34 - l41 * l31 - l42 * l32) * i33;

            const float d44 = g44 - l41 * l41 - l42 * l42 - l43 * l43;
            const float i44 = 1.0f / sqrtf(d44);

            const float y1 = b1 * i11;
            const float y2 = (b2 - l21 * y1) * i22;
            const float y3 = (b3 - l31 * y1 - l32 * y2) * i33;
            const float y4 = (b4 - l41 * y1 - l42 * y2 - l43 * y3) * i44;

            const float w4 = y4 * i44;
            const float w3 = (y3 - l43 * w4) * i33;
            const float w2 = (y2 - l32 * w3 - l42 * w4) * i22;
            const float w1 = (y1 - l21 * w2 - l31 * w3 - l41 * w4) * i11;

            out[T * TILE_BATCH + batchInTile] = make_float4(w1, w2, w3, w4);
        }

        // All reads of buf[p] done before it can be refilled at i+2.
        __syncthreads();
    }
}

extern "C" void kernel_launch(void* const* d_in, const int* in_sizes, int n_in,
                              void* d_out, int out_size)
{
    const float4* x = (const float4*)d_in[0];     // (B, 32, 4) fp32
    float4* out = (float4*)d_out;                 // (B, 4) fp32
    const int B = in_sizes[0] / (32 * 4);         // 262144
    const int nTiles = B / TILE_BATCH;            // 8192

    // One wave: 7 CTAs/SM x 152 SMs.
    int grid = 152 * 7;
    if (grid > nTiles) grid = nTiles;
    basic_ls_kernel<<<grid, 128>>>(x, out, nTiles);
}

// round 15
// speedup vs baseline: 1.2580x; 1.2580x over previous
#include <cuda_runtime.h>
#include <cuda_bf16.h>

// BasicLS: per-batch least squares.
// For each b: A = [-x[:,1:4], 1]  (32x4), r = x[:,0].
// out[b] = (A^T A)^{-1} A^T r   (4 floats), via normal equations + Cholesky.
//
// Champion structure (R7, 5834 GB/s — at the measured ~5.8 TB/s practical
// stream wall for this chip; cp.async / TMA / L2-hint / full-line-mapping
// alternatives all measured equal or worse):
//   - 4 threads per batch, 8 batches per warp.
//   - 8 front-batched LDG.128 per thread before any math (MLP_p1 = 8);
//     __launch_bounds__(256,4) gives the 64-reg budget that lets ptxas keep
//     them live. Reverse-order consumption defeats load-sinking.
//   - 2-step shfl_xor reduction over the 4-lane group; lane sub==0 solves
//     the 4x4 SPD system via rsqrt-form Cholesky and writes one float4.
// Micro-cleanups vs R7: exact grid (no bounds branch), rsqrtf Cholesky.

__global__ __launch_bounds__(256, 4)
void basic_ls_kernel(const float4* __restrict__ x,
                     float4* __restrict__ out)
{
    const int tid   = blockIdx.x * blockDim.x + threadIdx.x;
    const int warp  = tid >> 5;
    const int lane  = tid & 31;
    const int group = lane >> 2;   // batch within warp (0..7)
    const int sub   = lane & 3;    // row-group within batch (0..3)
    const int batch = warp * 8 + group;

    const float4* __restrict__ base = x + (size_t)batch * 32 + sub;

    // ---- Front-batched loads: 8 independent LDG.128 before ANY math. ----
    float4 v[8];
#pragma unroll
    for (int k = 0; k < 8; ++k)
        v[k] = __ldg(base + k * 4);

    // ---- Accumulate normal-equation sums (reverse order: first use of the
    //      earliest load comes last, defeating load-sinking). ----
    float sx1 = 0.f, sx2 = 0.f, sx3 = 0.f, sr = 0.f;
    float s11 = 0.f, s12 = 0.f, s13 = 0.f;
    float s22 = 0.f, s23 = 0.f, s33 = 0.f;
    float t1  = 0.f, t2  = 0.f, t3  = 0.f;

#pragma unroll
    for (int k = 7; k >= 0; --k) {
        const float r = v[k].x, a = v[k].y, b = v[k].z, c = v[k].w;
        sx1 += a;  sx2 += b;  sx3 += c;  sr += r;
        s11 = fmaf(a, a, s11);
        s12 = fmaf(a, b, s12);
        s13 = fmaf(a, c, s13);
        s22 = fmaf(b, b, s22);
        s23 = fmaf(b, c, s23);
        s33 = fmaf(c, c, s33);
        t1  = fmaf(a, r, t1);
        t2  = fmaf(b, r, t2);
        t3  = fmaf(c, r, t3);
    }

    // ---- Reduce the 13 sums across the 4-lane group (xor 1, then 2). ----
#pragma unroll
    for (int off = 1; off <= 2; off <<= 1) {
        sx1 += __shfl_xor_sync(0xffffffffu, sx1, off);
        sx2 += __shfl_xor_sync(0xffffffffu, sx2, off);
        sx3 += __shfl_xor_sync(0xffffffffu, sx3, off);
        sr  += __shfl_xor_sync(0xffffffffu, sr,  off);
        s11 += __shfl_xor_sync(0xffffffffu, s11, off);
        s12 += __shfl_xor_sync(0xffffffffu, s12, off);
        s13 += __shfl_xor_sync(0xffffffffu, s13, off);
        s22 += __shfl_xor_sync(0xffffffffu, s22, off);
        s23 += __shfl_xor_sync(0xffffffffu, s23, off);
        s33 += __shfl_xor_sync(0xffffffffu, s33, off);
        t1  += __shfl_xor_sync(0xffffffffu, t1,  off);
        t2  += __shfl_xor_sync(0xffffffffu, t2,  off);
        t3  += __shfl_xor_sync(0xffffffffu, t3,  off);
    }

    if (sub == 0) {
        // Normal equations with A = [-x1, -x2, -x3, 1]:
        const float g11 = s11, g12 = s12, g13 = s13, g14 = -sx1;
        const float g22 = s22, g23 = s23, g24 = -sx2;
        const float g33 = s33, g34 = -sx3;
        const float g44 = 32.0f;               // M rows, a4 == 1, no padding
        const float b1 = -t1, b2 = -t2, b3 = -t3, b4 = sr;

        // Cholesky in rsqrt form: i_jj = rsqrt(d_jj); L entries via multiply.
        const float i11 = rsqrtf(g11);
        const float l21 = g12 * i11;
        const float l31 = g13 * i11;
        const float l41 = g14 * i11;

        const float d22 = g22 - l21 * l21;
        const float i22 = rsqrtf(d22);
        const float l32 = (g23 - l31 * l21) * i22;
        const float l42 = (g24 - l41 * l21) * i22;

        const float d33 = g33 - l31 * l31 - l32 * l32;
        const float i33 = rsqrtf(d33);
        const float l43 = (g34 - l41 * l31 - l42 * l32) * i33;

        const float d44 = g44 - l41 * l41 - l42 * l42 - l43 * l43;
        const float i44 = rsqrtf(d44);

        // Forward solve L y = b
        const float y1 = b1 * i11;
        const float y2 = (b2 - l21 * y1) * i22;
        const float y3 = (b3 - l31 * y1 - l32 * y2) * i33;
        const float y4 = (b4 - l41 * y1 - l42 * y2 - l43 * y3) * i44;

        // Back solve L^T w = y
        const float w4 = y4 * i44;
        const float w3 = (y3 - l43 * w4) * i33;
        const float w2 = (y2 - l32 * w3 - l42 * w4) * i22;
        const float w1 = (y1 - l21 * w2 - l31 * w3 - l41 * w4) * i11;

        out[batch] = make_float4(w1, w2, w3, w4);
    }
}

extern "C" void kernel_launch(void* const* d_in, const int* in_sizes, int n_in,
                              void* d_out, int out_size)
{
    const float4* x = (const float4*)d_in[0];     // (B, 32, 4) fp32
    float4* out = (float4*)d_out;                 // (B, 4) fp32
    const int B = in_sizes[0] / (32 * 4);         // 262144

    // 4 threads per batch, 256 threads per block -> 64 batches per block.
    // B*4 is an exact multiple of 256 (B = 262144), so the grid is exact.
    const int threads = 256;
    const int blocks = (B * 4) / threads;
    basic_ls_kernel<<<blocks, threads>>>(x, out);
}